// round 4
// baseline (speedup 1.0000x reference)
#include <cuda_runtime.h>

#define FEATN   1024
#define NNODES  7
#define HIDN    64
#define NSCALES 5
#define BDIM    8192
#define DDIM    4096
#define NTREE   448      // 7*64
#define NDIR    256      // FEAT/4
#define NCAT    704      // 448+256

// Scratch (static device allocations are allowed)
__device__ float g_pre[(size_t)BDIM * NCAT];     // pre-activations: [B, 448 tree | 256 direct]
__device__ float g_gates[BDIM * NSCALES];        // final gates

typedef unsigned long long u64;

__device__ __forceinline__ u64 dup2(float x) {
    u64 r; asm("mov.b64 %0, {%1, %1};" : "=l"(r) : "f"(x)); return r;
}
__device__ __forceinline__ void ffma2(u64 &d, u64 a, u64 b) {
    asm("fma.rn.f32x2 %0, %1, %2, %0;" : "+l"(d) : "l"(a), "l"(b));
}
__device__ __forceinline__ void unpack2(u64 v, float &lo, float &hi) {
    asm("mov.b64 {%0, %1}, %2;" : "=f"(lo), "=f"(hi) : "l"(v));
}

// ---------------------------------------------------------------------------
// K1: fused SGEMM  C[B,704] = features @ [tw1;dw1]^T + bias   (f32x2 FFMA2)
// Tiles: BM=128, BN=128, BK=16, 256 threads, 8x8 per thread.
// Software-pipelined: next tile's global loads prefetched into registers
// during compute.
// ---------------------------------------------------------------------------
__global__ void __launch_bounds__(256, 2) gemm_kernel(
    const float* __restrict__ A,   // features [B, 1024]
    const float* __restrict__ Wt,  // tw1 viewed [448, 1024]
    const float* __restrict__ Wd,  // dw1 [256, 1024]
    const float* __restrict__ bt,  // tb1 [448]
    const float* __restrict__ bd)  // db1 [256]
{
    __shared__ __align__(16) float As[16][132];
    __shared__ __align__(16) float Bs[16][132];

    const int tid = threadIdx.x;
    const int rowBase = blockIdx.y * 128;
    const int colBase = blockIdx.x * 128;
    const int tx = tid & 15;        // N direction (8 cols each)
    const int ty = tid >> 4;        // M direction (8 rows each)

    u64 acc[4][8];
#pragma unroll
    for (int i = 0; i < 4; i++)
#pragma unroll
        for (int j = 0; j < 8; j++) acc[i][j] = 0ull;

    const int lrow = tid >> 2;           // 0..63
    const int kvo  = (tid & 3) * 4;      // float offset within BK=16

    const float* pA0 = A + (size_t)(rowBase + lrow) * FEATN;
    const float* pA1 = A + (size_t)(rowBase + lrow + 64) * FEATN;

    const int c0 = colBase + lrow;
    const int c1 = c0 + 64;
    const float* pB0 = (c0 < NTREE) ? (Wt + (size_t)c0 * FEATN)
                     : (c0 < NCAT)  ? (Wd + (size_t)(c0 - NTREE) * FEATN) : 0;
    const float* pB1 = (c1 < NTREE) ? (Wt + (size_t)c1 * FEATN)
                     : (c1 < NCAT)  ? (Wd + (size_t)(c1 - NTREE) * FEATN) : 0;

    const float4 z4 = make_float4(0.f, 0.f, 0.f, 0.f);

    // Prologue: prefetch tile 0
    float4 a0 = *(const float4*)(pA0 + kvo);
    float4 a1 = *(const float4*)(pA1 + kvo);
    float4 b0 = pB0 ? *(const float4*)(pB0 + kvo) : z4;
    float4 b1 = pB1 ? *(const float4*)(pB1 + kvo) : z4;

    for (int kt = 0; kt < FEATN / 16; kt++) {
        // Commit the prefetched tile to smem
        As[kvo + 0][lrow] = a0.x;  As[kvo + 1][lrow] = a0.y;
        As[kvo + 2][lrow] = a0.z;  As[kvo + 3][lrow] = a0.w;
        As[kvo + 0][lrow + 64] = a1.x;  As[kvo + 1][lrow + 64] = a1.y;
        As[kvo + 2][lrow + 64] = a1.z;  As[kvo + 3][lrow + 64] = a1.w;
        Bs[kvo + 0][lrow] = b0.x;  Bs[kvo + 1][lrow] = b0.y;
        Bs[kvo + 2][lrow] = b0.z;  Bs[kvo + 3][lrow] = b0.w;
        Bs[kvo + 0][lrow + 64] = b1.x;  Bs[kvo + 1][lrow + 64] = b1.y;
        Bs[kvo + 2][lrow + 64] = b1.z;  Bs[kvo + 3][lrow + 64] = b1.w;
        __syncthreads();

        // Prefetch next tile (overlaps with compute below)
        if (kt + 1 < FEATN / 16) {
            const int k = (kt + 1) * 16 + kvo;
            a0 = *(const float4*)(pA0 + k);
            a1 = *(const float4*)(pA1 + k);
            b0 = pB0 ? *(const float4*)(pB0 + k) : z4;
            b1 = pB1 ? *(const float4*)(pB1 + k) : z4;
        }

#pragma unroll
        for (int kk = 0; kk < 16; kk++) {
            const u64* pa = (const u64*)&As[kk][ty * 8];   // 4 row-pairs
            u64 a2[4];
#pragma unroll
            for (int i = 0; i < 4; i++) a2[i] = pa[i];
            const float4* pb = (const float4*)&Bs[kk][tx * 8];
            float4 bA = pb[0], bB = pb[1];
            u64 bb[8];
            bb[0] = dup2(bA.x); bb[1] = dup2(bA.y); bb[2] = dup2(bA.z); bb[3] = dup2(bA.w);
            bb[4] = dup2(bB.x); bb[5] = dup2(bB.y); bb[6] = dup2(bB.z); bb[7] = dup2(bB.w);
#pragma unroll
            for (int i = 0; i < 4; i++)
#pragma unroll
                for (int j = 0; j < 8; j++) ffma2(acc[i][j], a2[i], bb[j]);
        }
        __syncthreads();
    }

    // Epilogue: add bias, store fp32 pre-activations
#pragma unroll
    for (int j = 0; j < 8; j++) {
        const int col = colBase + tx * 8 + j;
        if (col >= NCAT) continue;
        const float bias = (col < NTREE) ? bt[col] : bd[col - NTREE];
#pragma unroll
        for (int i = 0; i < 4; i++) {
            float lo, hi;
            unpack2(acc[i][j], lo, hi);
            const int r0 = rowBase + ty * 8 + 2 * i;
            g_pre[(size_t)r0 * NCAT + col]       = lo + bias;
            g_pre[(size_t)(r0 + 1) * NCAT + col] = hi + bias;
        }
    }
}

// ---------------------------------------------------------------------------
// K2: per-row gating — LN + GELU + node softmax + tree product + leaf MLP +
//     direct MLP head + gate combination. One 256-thread block per row.
// ---------------------------------------------------------------------------
__global__ void gating_kernel(
    const float* __restrict__ tg,  const float* __restrict__ tbn,
    const float* __restrict__ tw2, const float* __restrict__ tb2,
    const float* __restrict__ lw1, const float* __restrict__ lb1,
    const float* __restrict__ lw2, const float* __restrict__ lb2,
    const float* __restrict__ dw2, const float* __restrict__ db2,
    const float* __restrict__ cw,
    float* gates_out)
{
    const int r = blockIdx.x;
    const int tid = threadIdx.x;
    const int lane = tid & 31;
    const int wid = tid >> 5;

    __shared__ float sh[NTREE];
    __shared__ float sd[NDIR];
    __shared__ float smu[NNODES], srs[NNODES];
    __shared__ float snp[NNODES * 2];
    __shared__ float sleaf[8], stt[10], sgt[5], sdl[5];

    const float* pre = g_pre + (size_t)r * NCAT;
    for (int i = tid; i < NTREE; i += 256) sh[i] = pre[i];
    sd[tid] = pre[NTREE + tid];
    __syncthreads();

    // Per-node mean / rstd (64 elems, warp n handles node n)
    if (wid < NNODES) {
        float v0 = sh[wid * 64 + lane], v1 = sh[wid * 64 + 32 + lane];
        float s = v0 + v1, q = v0 * v0 + v1 * v1;
#pragma unroll
        for (int o = 16; o; o >>= 1) {
            s += __shfl_xor_sync(~0u, s, o);
            q += __shfl_xor_sync(~0u, q, o);
        }
        if (lane == 0) {
            float mu = s * (1.0f / 64.0f);
            float var = q * (1.0f / 64.0f) - mu * mu;
            smu[wid] = mu;
            srs[wid] = rsqrtf(var + 1e-5f);
        }
    }
    __syncthreads();

    // LN + affine + exact GELU (tree) and exact GELU (direct)
    for (int i = tid; i < NTREE; i += 256) {
        const int n = i >> 6;
        float x = (sh[i] - smu[n]) * srs[n] * tg[i] + tbn[i];
        sh[i] = x * normcdff(x);
    }
    { float x = sd[tid]; sd[tid] = x * normcdff(x); }
    __syncthreads();

    // Node logits (2 per node) + softmax(logits / 0.5)
    if (wid < NNODES) {
        float h0 = sh[wid * 64 + lane], h1 = sh[wid * 64 + 32 + lane];
        float a0 = h0 * tw2[wid * 128 + lane]      + h1 * tw2[wid * 128 + 32 + lane];
        float a1 = h0 * tw2[wid * 128 + 64 + lane] + h1 * tw2[wid * 128 + 96 + lane];
#pragma unroll
        for (int o = 16; o; o >>= 1) {
            a0 += __shfl_xor_sync(~0u, a0, o);
            a1 += __shfl_xor_sync(~0u, a1, o);
        }
        if (lane == 0) {
            float l0 = (a0 + tb2[wid * 2])     * 2.0f;
            float l1 = (a1 + tb2[wid * 2 + 1]) * 2.0f;
            float m = fmaxf(l0, l1);
            float e0 = __expf(l0 - m), e1 = __expf(l1 - m);
            float inv = 1.0f / (e0 + e1);
            snp[wid * 2]     = e0 * inv;
            snp[wid * 2 + 1] = e1 * inv;
        }
    }
    __syncthreads();

    // Direct gate logits: warps 0..4 compute dot(dw2[s], sd)
    if (wid < NSCALES) {
        float a = 0.f;
        for (int j = lane; j < NDIR; j += 32) a += sd[j] * dw2[wid * NDIR + j];
#pragma unroll
        for (int o = 16; o; o >>= 1) a += __shfl_xor_sync(~0u, a, o);
        if (lane == 0) sdl[wid] = a + db2[wid];
    }

    // Tree chain: warp 7
    if (wid == 7) {
        if (lane < 8) {
            const int j0 = (lane >> 2) & 1, j1 = (lane >> 1) & 1, j2 = lane & 1;
            sleaf[lane] = snp[j0] * snp[(1 + j0) * 2 + j1] * snp[(3 + 2 * j0 + j1) * 2 + j2];
        }
        __syncwarp();
        if (lane < 10) {
            float t = lb1[lane];
#pragma unroll
            for (int l = 0; l < 8; l++) t += sleaf[l] * lw1[lane * 8 + l];
            stt[lane] = t * normcdff(t);
        }
        __syncwarp();
        if (lane < 5) {
            float g = lb2[lane];
#pragma unroll
            for (int l = 0; l < 10; l++) g += stt[l] * lw2[lane * 10 + l];
            sgt[lane] = g;
        }
        __syncwarp();
        if (lane == 0) {
            float m = sgt[0];
#pragma unroll
            for (int s = 1; s < 5; s++) m = fmaxf(m, sgt[s]);
            float e[5], sum = 0.f;
#pragma unroll
            for (int s = 0; s < 5; s++) { e[s] = __expf(sgt[s] - m); sum += e[s]; }
            float inv = 1.0f / sum;
#pragma unroll
            for (int s = 0; s < 5; s++) sgt[s] = e[s] * inv;
        }
    }
    __syncthreads();

    if (tid == 0) {
        float m = sdl[0];
#pragma unroll
        for (int s = 1; s < 5; s++) m = fmaxf(m, sdl[s]);
        float e[5], sum = 0.f;
#pragma unroll
        for (int s = 0; s < 5; s++) { e[s] = __expf(sdl[s] - m); sum += e[s]; }
        float inv = 1.0f / sum;
        float w = 1.0f / (1.0f + __expf(-cw[0]));
        float g[5], gs = 0.f;
#pragma unroll
        for (int s = 0; s < 5; s++) { g[s] = w * sgt[s] + (1.0f - w) * e[s] * inv; gs += g[s]; }
        float ginv = 1.0f / gs;
#pragma unroll
        for (int s = 0; s < 5; s++) {
            float gv = g[s] * ginv;
            g_gates[r * NSCALES + s] = gv;
            if (gates_out) gates_out[r * NSCALES + s] = gv;
        }
    }
}

// ---------------------------------------------------------------------------
// K3: combined[b,:] = sum_s gates[b,s] * logits[s,b,:]   (HBM-bound pass)
// One block per row, float4 vectorized.
// ---------------------------------------------------------------------------
__global__ void __launch_bounds__(256) combine_kernel(
    const float* __restrict__ logits, float* __restrict__ out)
{
    const int b = blockIdx.x;
    const int tid = threadIdx.x;
    __shared__ float sg[NSCALES];
    if (tid < NSCALES) sg[tid] = g_gates[b * NSCALES + tid];
    __syncthreads();
    const float g0 = sg[0], g1 = sg[1], g2 = sg[2], g3 = sg[3], g4 = sg[4];

    const size_t ps = (size_t)BDIM * (DDIM / 4);            // plane stride (float4)
    const float4* L = (const float4*)logits + (size_t)b * (DDIM / 4);
    float4* O = (float4*)out + (size_t)b * (DDIM / 4);

#pragma unroll
    for (int t = 0; t < 4; t++) {
        const int i = tid + t * 256;
        float4 v0 = L[i];
        float4 v1 = L[ps + i];
        float4 v2 = L[2 * ps + i];
        float4 v3 = L[3 * ps + i];
        float4 v4 = L[4 * ps + i];
        float4 r;
        r.x = g0 * v0.x + g1 * v1.x + g2 * v2.x + g3 * v3.x + g4 * v4.x;
        r.y = g0 * v0.y + g1 * v1.y + g2 * v2.y + g3 * v3.y + g4 * v4.y;
        r.z = g0 * v0.z + g1 * v1.z + g2 * v2.z + g3 * v3.z + g4 * v4.z;
        r.w = g0 * v0.w + g1 * v1.w + g2 * v2.w + g3 * v3.w + g4 * v4.w;
        O[i] = r;
    }
}

// ---------------------------------------------------------------------------
extern "C" void kernel_launch(void* const* d_in, const int* in_sizes, int n_in,
                              void* d_out, int out_size)
{
    const float* features = (const float*)d_in[0];
    const float* logits   = (const float*)d_in[1];
    const float* tw1      = (const float*)d_in[2];
    const float* tb1      = (const float*)d_in[3];
    const float* tg       = (const float*)d_in[4];
    const float* tbn      = (const float*)d_in[5];
    const float* tw2      = (const float*)d_in[6];
    const float* tb2      = (const float*)d_in[7];
    const float* lw1      = (const float*)d_in[8];
    const float* lb1      = (const float*)d_in[9];
    const float* lw2      = (const float*)d_in[10];
    const float* lb2      = (const float*)d_in[11];
    const float* dw1      = (const float*)d_in[12];
    const float* db1      = (const float*)d_in[13];
    const float* dw2      = (const float*)d_in[14];
    const float* db2      = (const float*)d_in[15];
    const float* cw       = (const float*)d_in[16];

    float* out = (float*)d_out;
    float* gates_out =
        ((size_t)out_size >= (size_t)BDIM * DDIM + (size_t)BDIM * NSCALES)
            ? out + (size_t)BDIM * DDIM : (float*)0;

    gemm_kernel<<<dim3(6, 64), 256>>>(features, tw1, dw1, tb1, db1);
    gating_kernel<<<BDIM, 256>>>(tg, tbn, tw2, tb2, lw1, lb1, lw2, lb2,
                                 dw2, db2, cw, gates_out);
    combine_kernel<<<BDIM, 256>>>(logits, out);
}

// round 7
// speedup vs baseline: 1.7154x; 1.7154x over previous
#include <cuda_runtime.h>
#include <cuda_bf16.h>
#include <cstdint>

#define FEATN   1024
#define NNODES  7
#define NSCALES 5
#define BDIM    8192
#define DDIM    4096
#define NTREE   448      // 7*64
#define NDIR    256      // FEAT/4
#define NCAT    704      // 448+256
#define NPAD    768      // padded output-col count (6*128)

#define BK      32
#define NKIT    (FEATN / BK)     // 32
#define LDSK    40               // padded smem row length in bf16 (80 B)
#define MAT_BYTES (128 * LDSK * 2)       // 10240 per matrix
#define BUF_BYTES (4 * MAT_BYTES)        // 40960 per stage (AH, AL, WH, WL)
#define DYN_SMEM  (2 * BUF_BYTES)        // 81920

// ---------------- scratch (static device allocations allowed) --------------
__device__ float g_pre[(size_t)BDIM * NCAT];
__device__ float g_gates[BDIM * NSCALES];
__device__ __nv_bfloat16 g_ah[(size_t)BDIM * FEATN];
__device__ __nv_bfloat16 g_al[(size_t)BDIM * FEATN];
__device__ __nv_bfloat16 g_wh[(size_t)NPAD * FEATN];
__device__ __nv_bfloat16 g_wl[(size_t)NPAD * FEATN];

// ---------------- helpers ----------------------------------------------
__device__ __forceinline__ uint32_t smem_u32(const void* p) {
    uint32_t a;
    asm("{ .reg .u64 t; cvta.to.shared.u64 t, %1; cvt.u32.u64 %0, t; }"
        : "=r"(a) : "l"(p));
    return a;
}
__device__ __forceinline__ void cpa16(uint32_t dst, const void* src) {
    asm volatile("cp.async.cg.shared.global [%0], [%1], 16;\n"
                 :: "r"(dst), "l"(src));
}
__device__ __forceinline__ void ldsm4(uint32_t& r0, uint32_t& r1,
                                      uint32_t& r2, uint32_t& r3, uint32_t a) {
    asm volatile("ldmatrix.sync.aligned.m8n8.x4.shared.b16 {%0,%1,%2,%3}, [%4];"
                 : "=r"(r0), "=r"(r1), "=r"(r2), "=r"(r3) : "r"(a));
}
__device__ __forceinline__ void mma16816(float* c, const uint32_t* a,
                                         const uint32_t* b) {
    asm volatile(
        "mma.sync.aligned.m16n8k16.row.col.f32.bf16.bf16.f32 "
        "{%0,%1,%2,%3}, {%4,%5,%6,%7}, {%8,%9}, {%0,%1,%2,%3};"
        : "+f"(c[0]), "+f"(c[1]), "+f"(c[2]), "+f"(c[3])
        : "r"(a[0]), "r"(a[1]), "r"(a[2]), "r"(a[3]), "r"(b[0]), "r"(b[1]));
}

// ---------------------------------------------------------------------------
// C0a: split features -> bf16 hi/lo
// ---------------------------------------------------------------------------
__global__ void __launch_bounds__(256) convA_kernel(const float* __restrict__ A) {
    const size_t base = (size_t)blockIdx.x * FEATN + threadIdx.x * 4;
    float4 v = *(const float4*)(A + base);
    __nv_bfloat16 h[4], l[4];
    float a[4] = {v.x, v.y, v.z, v.w};
#pragma unroll
    for (int i = 0; i < 4; i++) {
        h[i] = __float2bfloat16(a[i]);
        l[i] = __float2bfloat16(a[i] - __bfloat162float(h[i]));
    }
    *(uint2*)(g_ah + base) = *(const uint2*)h;
    *(uint2*)(g_al + base) = *(const uint2*)l;
}

// ---------------------------------------------------------------------------
// C0b: split [tw1;dw1] -> padded bf16 hi/lo (rows 704..767 zero)
// ---------------------------------------------------------------------------
__global__ void __launch_bounds__(256) convW_kernel(const float* __restrict__ tw1,
                                                    const float* __restrict__ dw1) {
    const int row = blockIdx.x;
    const size_t o = (size_t)row * FEATN + threadIdx.x * 4;
    __nv_bfloat16 h[4] = {}, l[4] = {};
    if (row < NCAT) {
        const float* src = (row < NTREE) ? (tw1 + (size_t)row * FEATN)
                                         : (dw1 + (size_t)(row - NTREE) * FEATN);
        float4 v = *(const float4*)(src + threadIdx.x * 4);
        float a[4] = {v.x, v.y, v.z, v.w};
#pragma unroll
        for (int i = 0; i < 4; i++) {
            h[i] = __float2bfloat16(a[i]);
            l[i] = __float2bfloat16(a[i] - __bfloat162float(h[i]));
        }
    }
    *(uint2*)(g_wh + o) = *(const uint2*)h;
    *(uint2*)(g_wl + o) = *(const uint2*)l;
}

// ---------------------------------------------------------------------------
// K1: bf16-split GEMM on legacy tensor path (mma.sync.m16n8k16).
//   g_pre[128x128 tile] = Ah·Wh^T + Al·Wh^T + Ah·Wl^T + bias
// 8 warps (2x4), warp tile 64x32, double-buffered cp.async, 80B smem rows.
// ---------------------------------------------------------------------------
__global__ void __launch_bounds__(256, 2) gemm_mma_kernel(
    const float* __restrict__ bt, const float* __restrict__ bd)
{
    extern __shared__ __align__(16) char dsm[];
    const uint32_t s0 = smem_u32(dsm);

    const int tid  = threadIdx.x;
    const int wid  = tid >> 5;
    const int lane = tid & 31;
    const int wy   = wid >> 2;            // 0..1  (64 rows each)
    const int wx   = wid & 3;             // 0..3  (32 cols each)
    const int rowBase = blockIdx.y * 128;
    const int colBase = blockIdx.x * 128;

    float acc[4][4][4];
#pragma unroll
    for (int m = 0; m < 4; m++)
#pragma unroll
        for (int n = 0; n < 4; n++)
#pragma unroll
            for (int i = 0; i < 4; i++) acc[m][n][i] = 0.f;

    // --- cp.async tile loader: 4 matrices x 2 chunks/thread -----------------
    const int lr = tid >> 2;            // 0..63
    const int lc = tid & 3;             // 16B chunk within 32-elem K slab
    // smem byte offsets within a matrix: row*80 + lc*16
    const uint32_t so0 = (uint32_t)lr * 80 + lc * 16;
    const uint32_t so1 = (uint32_t)(lr + 64) * 80 + lc * 16;

#define LOAD_STAGE(kt, b)                                                     \
    do {                                                                      \
        const uint32_t bb = s0 + (b) * BUF_BYTES;                             \
        const size_t gkA0 = (size_t)(rowBase + lr) * FEATN + (kt) * BK + lc * 8;      \
        const size_t gkA1 = (size_t)(rowBase + lr + 64) * FEATN + (kt) * BK + lc * 8; \
        const size_t gkW0 = (size_t)(colBase + lr) * FEATN + (kt) * BK + lc * 8;      \
        const size_t gkW1 = (size_t)(colBase + lr + 64) * FEATN + (kt) * BK + lc * 8; \
        cpa16(bb + so0,                 g_ah + gkA0);                         \
        cpa16(bb + so1,                 g_ah + gkA1);                         \
        cpa16(bb + MAT_BYTES + so0,     g_al + gkA0);                         \
        cpa16(bb + MAT_BYTES + so1,     g_al + gkA1);                         \
        cpa16(bb + 2 * MAT_BYTES + so0, g_wh + gkW0);                         \
        cpa16(bb + 2 * MAT_BYTES + so1, g_wh + gkW1);                         \
        cpa16(bb + 3 * MAT_BYTES + so0, g_wl + gkW0);                         \
        cpa16(bb + 3 * MAT_BYTES + so1, g_wl + gkW1);                         \
        asm volatile("cp.async.commit_group;" ::: "memory");                  \
    } while (0)

    // ldmatrix lane-address components (byte offsets within a matrix)
    // A atoms (m16k16): row = wy*64 + m*16 + lane%16 ; k = ks*16 + (lane/16)*8
    const uint32_t aoff = (uint32_t)(wy * 64 + (lane & 15)) * 80 + (lane >> 4) * 16;
    // B atoms x4 (two n8 atoms): t=lane/8:
    //   row = wx*32 + p*16 + (t>>1)*8 + lane%8 ; k = ks*16 + (t&1)*8
    const int bt_ = lane >> 3;
    const uint32_t boff = (uint32_t)(wx * 32 + ((bt_ >> 1) * 8) + (lane & 7)) * 80
                          + (bt_ & 1) * 16;

    LOAD_STAGE(0, 0);

    for (int kt = 0; kt < NKIT; kt++) {
        if (kt + 1 < NKIT) {
            LOAD_STAGE(kt + 1, (kt + 1) & 1);
            asm volatile("cp.async.wait_group 1;" ::: "memory");
        } else {
            asm volatile("cp.async.wait_group 0;" ::: "memory");
        }
        __syncthreads();

        const uint32_t bb = s0 + (kt & 1) * BUF_BYTES;
        const uint32_t baAH = bb + aoff;
        const uint32_t baAL = bb + MAT_BYTES + aoff;
        const uint32_t baWH = bb + 2 * MAT_BYTES + boff;
        const uint32_t baWL = bb + 3 * MAT_BYTES + boff;

#pragma unroll
        for (int ks = 0; ks < 2; ks++) {
            const uint32_t kso = ks * 32;   // 16 bf16 = 32 bytes
            uint32_t ah[4][4], bh[4][2], bl[4][2], al[4][4];
#pragma unroll
            for (int m = 0; m < 4; m++)
                ldsm4(ah[m][0], ah[m][1], ah[m][2], ah[m][3],
                      baAH + kso + m * (16 * 80));
#pragma unroll
            for (int p = 0; p < 2; p++) {
                uint32_t r0, r1, r2, r3;
                ldsm4(r0, r1, r2, r3, baWH + kso + p * (16 * 80));
                bh[2 * p][0] = r0; bh[2 * p][1] = r1;
                bh[2 * p + 1][0] = r2; bh[2 * p + 1][1] = r3;
            }
#pragma unroll
            for (int m = 0; m < 4; m++)
#pragma unroll
                for (int n = 0; n < 4; n++) mma16816(acc[m][n], ah[m], bh[n]);

#pragma unroll
            for (int p = 0; p < 2; p++) {
                uint32_t r0, r1, r2, r3;
                ldsm4(r0, r1, r2, r3, baWL + kso + p * (16 * 80));
                bl[2 * p][0] = r0; bl[2 * p][1] = r1;
                bl[2 * p + 1][0] = r2; bl[2 * p + 1][1] = r3;
            }
#pragma unroll
            for (int m = 0; m < 4; m++)
#pragma unroll
                for (int n = 0; n < 4; n++) mma16816(acc[m][n], ah[m], bl[n]);

#pragma unroll
            for (int m = 0; m < 4; m++)
                ldsm4(al[m][0], al[m][1], al[m][2], al[m][3],
                      baAL + kso + m * (16 * 80));
#pragma unroll
            for (int m = 0; m < 4; m++)
#pragma unroll
                for (int n = 0; n < 4; n++) mma16816(acc[m][n], al[m], bh[n]);
        }
        __syncthreads();
    }

    // --- epilogue: bias + store (float2, sector-contiguous) -----------------
    const int colT = colBase + wx * 32 + (lane & 3) * 2;
#pragma unroll
    for (int n = 0; n < 4; n++) {
        const int col = colT + n * 8;
        if (col >= NCAT) continue;
        const float b0 = (col < NTREE) ? bt[col] : bd[col - NTREE];
        const float b1 = (col + 1 < NTREE) ? bt[col + 1] : bd[col + 1 - NTREE];
#pragma unroll
        for (int m = 0; m < 4; m++) {
            const int r0 = rowBase + wy * 64 + m * 16 + (lane >> 2);
            float2 v0 = make_float2(acc[m][n][0] + b0, acc[m][n][1] + b1);
            float2 v1 = make_float2(acc[m][n][2] + b0, acc[m][n][3] + b1);
            *(float2*)(g_pre + (size_t)r0 * NCAT + col) = v0;
            *(float2*)(g_pre + (size_t)(r0 + 8) * NCAT + col) = v1;
        }
    }
#undef LOAD_STAGE
}

// ---------------------------------------------------------------------------
// K2: per-row gating — LN + GELU + node softmax + tree product + leaf MLP +
//     direct head + gate combination. One 256-thread block per row.
// ---------------------------------------------------------------------------
__global__ void gating_kernel(
    const float* __restrict__ tg,  const float* __restrict__ tbn,
    const float* __restrict__ tw2, const float* __restrict__ tb2,
    const float* __restrict__ lw1, const float* __restrict__ lb1,
    const float* __restrict__ lw2, const float* __restrict__ lb2,
    const float* __restrict__ dw2, const float* __restrict__ db2,
    const float* __restrict__ cw,
    float* gates_out)
{
    const int r = blockIdx.x;
    const int tid = threadIdx.x;
    const int lane = tid & 31;
    const int wid = tid >> 5;

    __shared__ float sh[NTREE];
    __shared__ float sd[NDIR];
    __shared__ float smu[NNODES], srs[NNODES];
    __shared__ float snp[NNODES * 2];
    __shared__ float sleaf[8], stt[10], sgt[5], sdl[5];

    const float* pre = g_pre + (size_t)r * NCAT;
    for (int i = tid; i < NTREE; i += 256) sh[i] = pre[i];
    sd[tid] = pre[NTREE + tid];
    __syncthreads();

    if (wid < NNODES) {
        float v0 = sh[wid * 64 + lane], v1 = sh[wid * 64 + 32 + lane];
        float s = v0 + v1, q = v0 * v0 + v1 * v1;
#pragma unroll
        for (int o = 16; o; o >>= 1) {
            s += __shfl_xor_sync(~0u, s, o);
            q += __shfl_xor_sync(~0u, q, o);
        }
        if (lane == 0) {
            float mu = s * (1.0f / 64.0f);
            float var = q * (1.0f / 64.0f) - mu * mu;
            smu[wid] = mu;
            srs[wid] = rsqrtf(var + 1e-5f);
        }
    }
    __syncthreads();

    for (int i = tid; i < NTREE; i += 256) {
        const int n = i >> 6;
        float x = (sh[i] - smu[n]) * srs[n] * tg[i] + tbn[i];
        sh[i] = x * normcdff(x);
    }
    { float x = sd[tid]; sd[tid] = x * normcdff(x); }
    __syncthreads();

    if (wid < NNODES) {
        float h0 = sh[wid * 64 + lane], h1 = sh[wid * 64 + 32 + lane];
        float a0 = h0 * tw2[wid * 128 + lane]      + h1 * tw2[wid * 128 + 32 + lane];
        float a1 = h0 * tw2[wid * 128 + 64 + lane] + h1 * tw2[wid * 128 + 96 + lane];
#pragma unroll
        for (int o = 16; o; o >>= 1) {
            a0 += __shfl_xor_sync(~0u, a0, o);
            a1 += __shfl_xor_sync(~0u, a1, o);
        }
        if (lane == 0) {
            float l0 = (a0 + tb2[wid * 2])     * 2.0f;
            float l1 = (a1 + tb2[wid * 2 + 1]) * 2.0f;
            float m = fmaxf(l0, l1);
            float e0 = __expf(l0 - m), e1 = __expf(l1 - m);
            float inv = 1.0f / (e0 + e1);
            snp[wid * 2]     = e0 * inv;
            snp[wid * 2 + 1] = e1 * inv;
        }
    }
    __syncthreads();

    if (wid < NSCALES) {
        float a = 0.f;
        for (int j = lane; j < NDIR; j += 32) a += sd[j] * dw2[wid * NDIR + j];
#pragma unroll
        for (int o = 16; o; o >>= 1) a += __shfl_xor_sync(~0u, a, o);
        if (lane == 0) sdl[wid] = a + db2[wid];
    }

    if (wid == 7) {
        if (lane < 8) {
            const int j0 = (lane >> 2) & 1, j1 = (lane >> 1) & 1, j2 = lane & 1;
            sleaf[lane] = snp[j0] * snp[(1 + j0) * 2 + j1] * snp[(3 + 2 * j0 + j1) * 2 + j2];
        }
        __syncwarp();
        if (lane < 10) {
            float t = lb1[lane];
#pragma unroll
            for (int l = 0; l < 8; l++) t += sleaf[l] * lw1[lane * 8 + l];
            stt[lane] = t * normcdff(t);
        }
        __syncwarp();
        if (lane < 5) {
            float g = lb2[lane];
#pragma unroll
            for (int l = 0; l < 10; l++) g += stt[l] * lw2[lane * 10 + l];
            sgt[lane] = g;
        }
        __syncwarp();
        if (lane == 0) {
            float m = sgt[0];
#pragma unroll
            for (int s = 1; s < 5; s++) m = fmaxf(m, sgt[s]);
            float e[5], sum = 0.f;
#pragma unroll
            for (int s = 0; s < 5; s++) { e[s] = __expf(sgt[s] - m); sum += e[s]; }
            float inv = 1.0f / sum;
#pragma unroll
            for (int s = 0; s < 5; s++) sgt[s] = e[s] * inv;
        }
    }
    __syncthreads();

    if (tid == 0) {
        float m = sdl[0];
#pragma unroll
        for (int s = 1; s < 5; s++) m = fmaxf(m, sdl[s]);
        float e[5], sum = 0.f;
#pragma unroll
        for (int s = 0; s < 5; s++) { e[s] = __expf(sdl[s] - m); sum += e[s]; }
        float inv = 1.0f / sum;
        float w = 1.0f / (1.0f + __expf(-cw[0]));
        float g[5], gs = 0.f;
#pragma unroll
        for (int s = 0; s < 5; s++) { g[s] = w * sgt[s] + (1.0f - w) * e[s] * inv; gs += g[s]; }
        float ginv = 1.0f / gs;
#pragma unroll
        for (int s = 0; s < 5; s++) {
            float gv = g[s] * ginv;
            g_gates[r * NSCALES + s] = gv;
            if (gates_out) gates_out[r * NSCALES + s] = gv;
        }
    }
}

// ---------------------------------------------------------------------------
// K3: combined[b,:] = sum_s gates[b,s] * logits[s,b,:]   (HBM-bound pass)
// ---------------------------------------------------------------------------
__global__ void __launch_bounds__(256) combine_kernel(
    const float* __restrict__ logits, float* __restrict__ out)
{
    const int b = blockIdx.x;
    const int tid = threadIdx.x;
    __shared__ float sg[NSCALES];
    if (tid < NSCALES) sg[tid] = g_gates[b * NSCALES + tid];
    __syncthreads();
    const float g0 = sg[0], g1 = sg[1], g2 = sg[2], g3 = sg[3], g4 = sg[4];

    const size_t ps = (size_t)BDIM * (DDIM / 4);
    const float4* L = (const float4*)logits + (size_t)b * (DDIM / 4);
    float4* O = (float4*)out + (size_t)b * (DDIM / 4);

#pragma unroll
    for (int t = 0; t < 4; t++) {
        const int i = tid + t * 256;
        float4 v0 = L[i];
        float4 v1 = L[ps + i];
        float4 v2 = L[2 * ps + i];
        float4 v3 = L[3 * ps + i];
        float4 v4 = L[4 * ps + i];
        float4 r;
        r.x = g0 * v0.x + g1 * v1.x + g2 * v2.x + g3 * v3.x + g4 * v4.x;
        r.y = g0 * v0.y + g1 * v1.y + g2 * v2.y + g3 * v3.y + g4 * v4.y;
        r.z = g0 * v0.z + g1 * v1.z + g2 * v2.z + g3 * v3.z + g4 * v4.z;
        r.w = g0 * v0.w + g1 * v1.w + g2 * v2.w + g3 * v3.w + g4 * v4.w;
        O[i] = r;
    }
}

// ---------------------------------------------------------------------------
extern "C" void kernel_launch(void* const* d_in, const int* in_sizes, int n_in,
                              void* d_out, int out_size)
{
    const float* features = (const float*)d_in[0];
    const float* logits   = (const float*)d_in[1];
    const float* tw1      = (const float*)d_in[2];
    const float* tb1      = (const float*)d_in[3];
    const float* tg       = (const float*)d_in[4];
    const float* tbn      = (const float*)d_in[5];
    const float* tw2      = (const float*)d_in[6];
    const float* tb2      = (const float*)d_in[7];
    const float* lw1      = (const float*)d_in[8];
    const float* lb1      = (const float*)d_in[9];
    const float* lw2      = (const float*)d_in[10];
    const float* lb2      = (const float*)d_in[11];
    const float* dw1      = (const float*)d_in[12];
    const float* db1      = (const float*)d_in[13];
    const float* dw2      = (const float*)d_in[14];
    const float* db2      = (const float*)d_in[15];
    const float* cw       = (const float*)d_in[16];

    float* out = (float*)d_out;
    float* gates_out =
        ((size_t)out_size >= (size_t)BDIM * DDIM + (size_t)BDIM * NSCALES)
            ? out + (size_t)BDIM * DDIM : (float*)0;

    cudaFuncSetAttribute(gemm_mma_kernel,
                         cudaFuncAttributeMaxDynamicSharedMemorySize, DYN_SMEM);

    convA_kernel<<<BDIM, 256>>>(features);
    convW_kernel<<<NPAD, 256>>>(tw1, dw1);
    gemm_mma_kernel<<<dim3(6, 64), 256, DYN_SMEM>>>(tb1, db1);
    gating_kernel<<<BDIM, 256>>>(tg, tbn, tw2, tb2, lw1, lb1, lw2, lb2,
                                 dw2, db2, cw, gates_out);
    combine_kernel<<<BDIM, 256>>>(logits, out);
}